// round 1
// baseline (speedup 1.0000x reference)
#include <cuda_runtime.h>
#include <math.h>

// Problem sizes (fixed by the dataset)
#define NN 4096
#define MM 8192
#define DD 512
#define INV_REG 10.0f           // 1/reg, reg = 0.1
#define N_ITERS 200
#define LOGA   (-8.317766166719343f)   // -log(4096)  (f' = f/reg = loga - LSE)
#define CHUNKS 64               // row chunks for the column-LSE partial pass

// ---------------- device scratch (no allocations allowed) ----------------
__device__ __align__(16) float d_C[(size_t)NN * MM];   // 128 MB cost matrix
__device__ __align__(16) float d_f[NN];
__device__ __align__(16) float d_g[MM];
__device__ __align__(16) float d_logb[MM];
__device__ __align__(16) float d_xsq[NN];
__device__ __align__(16) float d_ysq[MM];
__device__ __align__(16) float d_pm[(size_t)CHUNKS * MM];
__device__ __align__(16) float d_ps[(size_t)CHUNKS * MM];
__device__ double d_ot;
__device__ double d_sq;
__device__ double d_cnt;
__device__ int    d_is64;

// ---------------- streaming logsumexp helpers ----------------
__device__ __forceinline__ void lse_add(float x, float& m, float& s) {
    if (x <= m) {
        s += __expf(x - m);
    } else {
        s = fmaf(s, __expf(m - x), 1.0f);
        m = x;
    }
}
__device__ __forceinline__ void lse_merge(float mo, float so, float& m, float& s) {
    float mn = fmaxf(m, mo);
    s = s * __expf(m - mn) + so * __expf(mo - mn);
    m = mn;
}

// ---------------- init: tgt sum -> logb, zero g, zero accumulators, dtype detect ----------------
__global__ void k_init(const float* __restrict__ tgt, const int* __restrict__ al_raw) {
    __shared__ float red[32];
    __shared__ float s_total;
    int t = threadIdx.x;                       // 1024 threads, 1 block
    float s = 0.f;
    for (int j = t; j < MM; j += 1024) s += tgt[j];
    #pragma unroll
    for (int o = 16; o; o >>= 1) s += __shfl_down_sync(0xffffffffu, s, o);
    if ((t & 31) == 0) red[t >> 5] = s;
    __syncthreads();
    if (t < 32) {
        float v = red[t];
        #pragma unroll
        for (int o = 16; o; o >>= 1) v += __shfl_down_sync(0xffffffffu, v, o);
        if (t == 0) s_total = v;
    }
    __syncthreads();
    float lt = logf(s_total);
    for (int j = t; j < MM; j += 1024) {
        d_logb[j] = logf(tgt[j]) - lt;         // log(b_j); g' = logb - LSE
        d_g[j] = 0.f;
    }
    // int64-vs-int32 detection for `aligned`: read only first 16KB (safe either way).
    // int64 little-endian with values in [0, 2^31) => every odd 32-bit word is 0.
    int odd_nz = 0;
    for (int i = t; i < NN / 2; i += 1024)
        if (al_raw[2 * i + 1] != 0) odd_nz = 1;
    odd_nz = __syncthreads_or(odd_nz);
    if (t == 0) {
        d_is64 = odd_nz ? 0 : 1;
        d_ot = 0.0; d_sq = 0.0; d_cnt = 0.0;
    }
}

// ---------------- row squared norms ----------------
__global__ __launch_bounds__(128) void k_sqnorm(const float* __restrict__ X, int which) {
    int row = blockIdx.x, t = threadIdx.x;     // 128 threads, D/4 = 128 float4
    float4 v = ((const float4*)X)[(size_t)row * (DD / 4) + t];
    float s = v.x * v.x + v.y * v.y + v.z * v.z + v.w * v.w;
    #pragma unroll
    for (int o = 16; o; o >>= 1) s += __shfl_down_sync(0xffffffffu, s, o);
    __shared__ float red[4];
    if ((t & 31) == 0) red[t >> 5] = s;
    __syncthreads();
    if (t == 0) {
        float tot = red[0] + red[1] + red[2] + red[3];
        if (which == 0) d_xsq[row] = tot; else d_ysq[row] = tot;
    }
}

// ---------------- tiled fp32 GEMM + cdist epilogue: C = sqrt(max(xsq+ysq-2 X.Y^T, 1e-12)) ----------------
__global__ __launch_bounds__(256) void k_gemm(const float* __restrict__ X, const float* __restrict__ Y) {
    __shared__ float As[16][128];
    __shared__ float Bs[16][128];
    int tid = threadIdx.x;
    int bx = blockIdx.x;     // M tiles (64)
    int by = blockIdx.y;     // N tiles (32)
    int tx = tid & 15, ty = tid >> 4;
    float acc[8][8];
    #pragma unroll
    for (int i = 0; i < 8; i++)
        #pragma unroll
        for (int j = 0; j < 8; j++) acc[i][j] = 0.f;

    const float* Xb = X + (size_t)by * 128 * DD;
    const float* Yb = Y + (size_t)bx * 128 * DD;

    for (int kt = 0; kt < DD; kt += 16) {
        __syncthreads();
        #pragma unroll
        for (int i = 0; i < 2; i++) {
            int l  = tid + i * 256;   // 0..511
            int r  = l >> 2;          // 0..127
            int c4 = l & 3;           // 0..3
            float4 va = *(const float4*)(Xb + (size_t)r * DD + kt + c4 * 4);
            As[c4 * 4 + 0][r] = va.x; As[c4 * 4 + 1][r] = va.y;
            As[c4 * 4 + 2][r] = va.z; As[c4 * 4 + 3][r] = va.w;
            float4 vb = *(const float4*)(Yb + (size_t)r * DD + kt + c4 * 4);
            Bs[c4 * 4 + 0][r] = vb.x; Bs[c4 * 4 + 1][r] = vb.y;
            Bs[c4 * 4 + 2][r] = vb.z; Bs[c4 * 4 + 3][r] = vb.w;
        }
        __syncthreads();
        #pragma unroll
        for (int kk = 0; kk < 16; kk++) {
            float a[8], b[8];
            *(float4*)(a)     = *(const float4*)&As[kk][ty * 8];
            *(float4*)(a + 4) = *(const float4*)&As[kk][ty * 8 + 4];
            *(float4*)(b)     = *(const float4*)&Bs[kk][tx * 8];
            *(float4*)(b + 4) = *(const float4*)&Bs[kk][tx * 8 + 4];
            #pragma unroll
            for (int i = 0; i < 8; i++)
                #pragma unroll
                for (int j = 0; j < 8; j++)
                    acc[i][j] = fmaf(a[i], b[j], acc[i][j]);
        }
    }
    int i0 = by * 128 + ty * 8;
    int j0 = bx * 128 + tx * 8;
    float ys[8];
    #pragma unroll
    for (int jj = 0; jj < 8; jj++) ys[jj] = d_ysq[j0 + jj];
    #pragma unroll
    for (int ii = 0; ii < 8; ii++) {
        float xs = d_xsq[i0 + ii];
        float o[8];
        #pragma unroll
        for (int jj = 0; jj < 8; jj++) {
            float sq = xs + ys[jj] - 2.0f * acc[ii][jj];
            o[jj] = sqrtf(fmaxf(sq, 1e-12f));
        }
        float4* dst = (float4*)(d_C + (size_t)(i0 + ii) * MM + j0);
        dst[0] = make_float4(o[0], o[1], o[2], o[3]);
        dst[1] = make_float4(o[4], o[5], o[6], o[7]);
    }
}

// ---------------- f update: row logsumexp of (g' - C/reg) ----------------
__global__ __launch_bounds__(256) void k_frow() {
    int row = blockIdx.x;
    int t = threadIdx.x;
    const float4* C4 = (const float4*)(d_C + (size_t)row * MM);
    const float4* G4 = (const float4*)d_g;
    float m = -1e30f, s = 0.f;
    #pragma unroll
    for (int k = 0; k < 8; k++) {
        int idx = t + k * 256;
        float4 cv = C4[idx];
        float4 gv = G4[idx];     // 32KB vector, L1-resident
        lse_add(fmaf(cv.x, -INV_REG, gv.x), m, s);
        lse_add(fmaf(cv.y, -INV_REG, gv.y), m, s);
        lse_add(fmaf(cv.z, -INV_REG, gv.z), m, s);
        lse_add(fmaf(cv.w, -INV_REG, gv.w), m, s);
    }
    #pragma unroll
    for (int o = 16; o; o >>= 1) {
        float mo = __shfl_down_sync(0xffffffffu, m, o);
        float so = __shfl_down_sync(0xffffffffu, s, o);
        lse_merge(mo, so, m, s);
    }
    __shared__ float smm[8], sms[8];
    int lane = t & 31, w = t >> 5;
    if (lane == 0) { smm[w] = m; sms[w] = s; }
    __syncthreads();
    if (w == 0) {
        m = (lane < 8) ? smm[lane] : -1e30f;
        s = (lane < 8) ? sms[lane] : 0.f;
        #pragma unroll
        for (int o = 4; o; o >>= 1) {
            float mo = __shfl_down_sync(0xffffffffu, m, o);
            float so = __shfl_down_sync(0xffffffffu, s, o);
            lse_merge(mo, so, m, s);
        }
        if (t == 0) d_f[row] = LOGA - (m + logf(s));
    }
}

// ---------------- g update stage 1: per-chunk column LSE partials ----------------
__global__ __launch_bounds__(256) void k_gpart() {
    int t = threadIdx.x;
    int j = blockIdx.x * 1024 + t * 4;
    int r0 = blockIdx.y * (NN / CHUNKS);     // 64 rows per chunk
    float m0 = -1e30f, m1 = -1e30f, m2 = -1e30f, m3 = -1e30f;
    float s0 = 0.f, s1 = 0.f, s2 = 0.f, s3 = 0.f;
    const float* Cb = d_C + j;
    #pragma unroll 4
    for (int r = r0; r < r0 + (NN / CHUNKS); r++) {
        float fr = __ldg(&d_f[r]);
        float4 cv = *(const float4*)(Cb + (size_t)r * MM);
        lse_add(fmaf(cv.x, -INV_REG, fr), m0, s0);
        lse_add(fmaf(cv.y, -INV_REG, fr), m1, s1);
        lse_add(fmaf(cv.z, -INV_REG, fr), m2, s2);
        lse_add(fmaf(cv.w, -INV_REG, fr), m3, s3);
    }
    size_t o = (size_t)blockIdx.y * MM + j;
    *(float4*)(d_pm + o) = make_float4(m0, m1, m2, m3);
    *(float4*)(d_ps + o) = make_float4(s0, s1, s2, s3);
}

// ---------------- g update stage 2: combine partials ----------------
__global__ __launch_bounds__(256) void k_gcomb() {
    int j = blockIdx.x * 256 + threadIdx.x;
    float m = -1e30f, s = 0.f;
    #pragma unroll 8
    for (int c = 0; c < CHUNKS; c++)
        lse_merge(__ldg(&d_pm[(size_t)c * MM + j]), __ldg(&d_ps[(size_t)c * MM + j]), m, s);
    d_g[j] = d_logb[j] - (m + logf(s));
}

// ---------------- final OT loss: sum exp(f'+g'-C/reg) * C ----------------
__global__ __launch_bounds__(256) void k_ot() {
    int t = threadIdx.x;
    int j = blockIdx.x * 1024 + t * 4;
    int r0 = blockIdx.y * (NN / CHUNKS);
    float4 gv = *(const float4*)(d_g + j);
    float acc = 0.f;
    #pragma unroll 4
    for (int r = r0; r < r0 + (NN / CHUNKS); r++) {
        float fr = __ldg(&d_f[r]);
        float4 cv = *(const float4*)(d_C + (size_t)r * MM + j);
        acc += __expf(fmaf(cv.x, -INV_REG, fr + gv.x)) * cv.x;
        acc += __expf(fmaf(cv.y, -INV_REG, fr + gv.y)) * cv.y;
        acc += __expf(fmaf(cv.z, -INV_REG, fr + gv.z)) * cv.z;
        acc += __expf(fmaf(cv.w, -INV_REG, fr + gv.w)) * cv.w;
    }
    double da = (double)acc;
    #pragma unroll
    for (int o = 16; o; o >>= 1) da += __shfl_down_sync(0xffffffffu, da, o);
    __shared__ double sd[8];
    int lane = t & 31, w = t >> 5;
    if (lane == 0) sd[w] = da;
    __syncthreads();
    if (t == 0) {
        double tot = 0.0;
        #pragma unroll
        for (int k = 0; k < 8; k++) tot += sd[k];
        atomicAdd(&d_ot, tot);
    }
}

// ---------------- supervised alignment MSE ----------------
__global__ __launch_bounds__(128) void k_dist(const float* __restrict__ X,
                                              const float* __restrict__ W,
                                              const int* __restrict__ al) {
    int row = blockIdx.x, t = threadIdx.x;
    long long idx; int mask;
    if (d_is64) {
        long long v = ((const long long*)al)[row];
        mask = (v != -1LL);
        idx = v < 0 ? 0 : v;
    } else {
        int v = al[row];
        mask = (v != -1);
        idx = v < 0 ? 0 : (long long)v;
    }
    float4 a = ((const float4*)X)[(size_t)row * (DD / 4) + t];
    float4 b = ((const float4*)W)[(size_t)idx * (DD / 4) + t];
    float dx = a.x - b.x, dy = a.y - b.y, dz = a.z - b.z, dw = a.w - b.w;
    float s = dx * dx + dy * dy + dz * dz + dw * dw;
    #pragma unroll
    for (int o = 16; o; o >>= 1) s += __shfl_down_sync(0xffffffffu, s, o);
    __shared__ float red[4];
    if ((t & 31) == 0) red[t >> 5] = s;
    __syncthreads();
    if (t == 0) {
        float tot = red[0] + red[1] + red[2] + red[3];
        if (mask) {
            atomicAdd(&d_sq, (double)tot);
            atomicAdd(&d_cnt, 1.0);
        }
    }
}

// ---------------- finalize ----------------
__global__ void k_final(float* out) {
    double dl = (d_cnt > 0.0) ? d_sq / (d_cnt * (double)DD) : 0.0;
    out[0] = (float)(d_ot + dl);
}

// ---------------- launch ----------------
extern "C" void kernel_launch(void* const* d_in, const int* in_sizes, int n_in,
                              void* d_out, int out_size) {
    const float* X  = (const float*)d_in[0];   // descriptors   (4096, 512)
    const float* W  = (const float*)d_in[1];   // word_embeds   (8192, 512)
    const int*   AL = (const int*)d_in[2];     // aligned       (4096,) int32 or int64
    const float* T  = (const float*)d_in[3];   // tgt_probs     (8192,)
    float* out = (float*)d_out;

    k_init<<<1, 1024>>>(T, AL);
    k_sqnorm<<<NN, 128>>>(X, 0);
    k_sqnorm<<<MM, 128>>>(W, 1);
    dim3 gg(MM / 128, NN / 128);
    k_gemm<<<gg, 256>>>(X, W);

    for (int it = 0; it < N_ITERS; it++) {
        k_frow<<<NN, 256>>>();
        k_gpart<<<dim3(MM / 1024, CHUNKS), 256>>>();
        k_gcomb<<<MM / 256, 256>>>();
    }

    k_ot<<<dim3(MM / 1024, CHUNKS), 256>>>();
    k_dist<<<NN, 128>>>(X, W, AL);
    k_final<<<1, 1>>>(out);
}

// round 2
// speedup vs baseline: 1.6599x; 1.6599x over previous
#include <cuda_runtime.h>
#include <math.h>

// Problem sizes (fixed by the dataset)
#define NN 4096
#define MM 8192
#define DD 512
#define INV_REG 10.0f           // 1/reg, reg = 0.1
#define N_ITERS 200
#define LOGA   (-8.317766166719343f)   // -log(4096)  (f' = f/reg = loga - LSE)
#define CHUNKS 64               // row chunks for the column-LSE partial pass
#define ROWS_PER_FBLK 8

// ---------------- device scratch (no allocations allowed) ----------------
__device__ __align__(16) float d_C[(size_t)NN * MM];   // 128 MB cost matrix
__device__ __align__(16) float d_f[NN];
__device__ __align__(16) float d_g[MM];
__device__ __align__(16) float d_logb[MM];
__device__ __align__(16) float d_xsq[NN];
__device__ __align__(16) float d_ysq[MM];
__device__ __align__(16) float d_pm[(size_t)CHUNKS * MM];
__device__ __align__(16) float d_ps[(size_t)CHUNKS * MM];
__device__ double d_ot;
__device__ double d_sq;
__device__ double d_cnt;
__device__ int    d_is64;

__device__ __forceinline__ void lse_merge(float mo, float so, float& m, float& s) {
    float mn = fmaxf(m, mo);
    s = s * __expf(m - mn) + so * __expf(mo - mn);
    m = mn;
}

// ---------------- init: tgt sum -> logb, zero g, zero accumulators, dtype detect ----------------
__global__ void k_init(const float* __restrict__ tgt, const int* __restrict__ al_raw) {
    __shared__ float red[32];
    __shared__ float s_total;
    int t = threadIdx.x;                       // 1024 threads, 1 block
    float s = 0.f;
    for (int j = t; j < MM; j += 1024) s += tgt[j];
    #pragma unroll
    for (int o = 16; o; o >>= 1) s += __shfl_down_sync(0xffffffffu, s, o);
    if ((t & 31) == 0) red[t >> 5] = s;
    __syncthreads();
    if (t < 32) {
        float v = red[t];
        #pragma unroll
        for (int o = 16; o; o >>= 1) v += __shfl_down_sync(0xffffffffu, v, o);
        if (t == 0) s_total = v;
    }
    __syncthreads();
    float lt = logf(s_total);
    for (int j = t; j < MM; j += 1024) {
        d_logb[j] = logf(tgt[j]) - lt;         // log(b_j); g' = logb - LSE
        d_g[j] = 0.f;
    }
    // int64-vs-int32 detection for `aligned` (values in [0, 2^31) => odd words all 0)
    int odd_nz = 0;
    for (int i = t; i < NN / 2; i += 1024)
        if (al_raw[2 * i + 1] != 0) odd_nz = 1;
    odd_nz = __syncthreads_or(odd_nz);
    if (t == 0) {
        d_is64 = odd_nz ? 0 : 1;
        d_ot = 0.0; d_sq = 0.0; d_cnt = 0.0;
    }
}

// ---------------- row squared norms ----------------
__global__ __launch_bounds__(128) void k_sqnorm(const float* __restrict__ X, int which) {
    int row = blockIdx.x, t = threadIdx.x;
    float4 v = ((const float4*)X)[(size_t)row * (DD / 4) + t];
    float s = v.x * v.x + v.y * v.y + v.z * v.z + v.w * v.w;
    #pragma unroll
    for (int o = 16; o; o >>= 1) s += __shfl_down_sync(0xffffffffu, s, o);
    __shared__ float red[4];
    if ((t & 31) == 0) red[t >> 5] = s;
    __syncthreads();
    if (t == 0) {
        float tot = red[0] + red[1] + red[2] + red[3];
        if (which == 0) d_xsq[row] = tot; else d_ysq[row] = tot;
    }
}

// ---------------- tiled fp32 GEMM + cdist epilogue ----------------
__global__ __launch_bounds__(256) void k_gemm(const float* __restrict__ X, const float* __restrict__ Y) {
    __shared__ float As[16][128];
    __shared__ float Bs[16][128];
    int tid = threadIdx.x;
    int bx = blockIdx.x;     // M tiles (64)
    int by = blockIdx.y;     // N tiles (32)
    int tx = tid & 15, ty = tid >> 4;
    float acc[8][8];
    #pragma unroll
    for (int i = 0; i < 8; i++)
        #pragma unroll
        for (int j = 0; j < 8; j++) acc[i][j] = 0.f;

    const float* Xb = X + (size_t)by * 128 * DD;
    const float* Yb = Y + (size_t)bx * 128 * DD;

    for (int kt = 0; kt < DD; kt += 16) {
        __syncthreads();
        #pragma unroll
        for (int i = 0; i < 2; i++) {
            int l  = tid + i * 256;
            int r  = l >> 2;
            int c4 = l & 3;
            float4 va = *(const float4*)(Xb + (size_t)r * DD + kt + c4 * 4);
            As[c4 * 4 + 0][r] = va.x; As[c4 * 4 + 1][r] = va.y;
            As[c4 * 4 + 2][r] = va.z; As[c4 * 4 + 3][r] = va.w;
            float4 vb = *(const float4*)(Yb + (size_t)r * DD + kt + c4 * 4);
            Bs[c4 * 4 + 0][r] = vb.x; Bs[c4 * 4 + 1][r] = vb.y;
            Bs[c4 * 4 + 2][r] = vb.z; Bs[c4 * 4 + 3][r] = vb.w;
        }
        __syncthreads();
        #pragma unroll
        for (int kk = 0; kk < 16; kk++) {
            float a[8], b[8];
            *(float4*)(a)     = *(const float4*)&As[kk][ty * 8];
            *(float4*)(a + 4) = *(const float4*)&As[kk][ty * 8 + 4];
            *(float4*)(b)     = *(const float4*)&Bs[kk][tx * 8];
            *(float4*)(b + 4) = *(const float4*)&Bs[kk][tx * 8 + 4];
            #pragma unroll
            for (int i = 0; i < 8; i++)
                #pragma unroll
                for (int j = 0; j < 8; j++)
                    acc[i][j] = fmaf(a[i], b[j], acc[i][j]);
        }
    }
    int i0 = by * 128 + ty * 8;
    int j0 = bx * 128 + tx * 8;
    float ys[8];
    #pragma unroll
    for (int jj = 0; jj < 8; jj++) ys[jj] = d_ysq[j0 + jj];
    #pragma unroll
    for (int ii = 0; ii < 8; ii++) {
        float xs = d_xsq[i0 + ii];
        float o[8];
        #pragma unroll
        for (int jj = 0; jj < 8; jj++) {
            float sq = xs + ys[jj] - 2.0f * acc[ii][jj];
            o[jj] = sqrtf(fmaxf(sq, 1e-12f));
        }
        float4* dst = (float4*)(d_C + (size_t)(i0 + ii) * MM + j0);
        dst[0] = make_float4(o[0], o[1], o[2], o[3]);
        dst[1] = make_float4(o[4], o[5], o[6], o[7]);
    }
}

// ---------------- f update: row logsumexp of (g' - C/reg) ----------------
// 8 rows per block, g staged in smem, register-batched branchless LSE.
__global__ __launch_bounds__(256) void k_frow() {
    __shared__ float sg[MM];         // 32 KB
    __shared__ float red_m[8], red_s[8];
    int t = threadIdx.x;
    int lane = t & 31, w = t >> 5;

    // stage g once per block
    #pragma unroll
    for (int k = 0; k < 8; k++)
        ((float4*)sg)[t + k * 256] = ((const float4*)d_g)[t + k * 256];
    __syncthreads();

    int row0 = blockIdx.x * ROWS_PER_FBLK;
    for (int rr = 0; rr < ROWS_PER_FBLK; rr++) {
        int row = row0 + rr;
        const float4* C4 = (const float4*)(d_C + (size_t)row * MM);

        float x[32];
        #pragma unroll
        for (int k = 0; k < 8; k++) {
            float4 cv = C4[t + k * 256];
            float4 gv = ((const float4*)sg)[t + k * 256];
            x[k * 4 + 0] = fmaf(cv.x, -INV_REG, gv.x);
            x[k * 4 + 1] = fmaf(cv.y, -INV_REG, gv.y);
            x[k * 4 + 2] = fmaf(cv.z, -INV_REG, gv.z);
            x[k * 4 + 3] = fmaf(cv.w, -INV_REG, gv.w);
        }
        // thread max
        float m = x[0];
        #pragma unroll
        for (int i = 1; i < 32; i++) m = fmaxf(m, x[i]);
        // warp max
        #pragma unroll
        for (int o = 16; o; o >>= 1) m = fmaxf(m, __shfl_xor_sync(0xffffffffu, m, o));
        // exp-sum with warp-uniform shift (4 independent accumulators)
        float s0 = 0.f, s1 = 0.f, s2 = 0.f, s3 = 0.f;
        #pragma unroll
        for (int i = 0; i < 32; i += 4) {
            s0 += __expf(x[i + 0] - m);
            s1 += __expf(x[i + 1] - m);
            s2 += __expf(x[i + 2] - m);
            s3 += __expf(x[i + 3] - m);
        }
        float s = (s0 + s1) + (s2 + s3);
        #pragma unroll
        for (int o = 16; o; o >>= 1) s += __shfl_down_sync(0xffffffffu, s, o);
        if (lane == 0) { red_m[w] = m; red_s[w] = s; }
        __syncthreads();
        if (t == 0) {
            float fm = red_m[0], fs = red_s[0];
            #pragma unroll
            for (int k = 1; k < 8; k++) lse_merge(red_m[k], red_s[k], fm, fs);
            d_f[row] = LOGA - (fm + logf(fs));
        }
        __syncthreads();
    }
}

// ---------------- g update stage 1: per-chunk column LSE partials ----------------
// 8-row register batching, batch-max then single-shift merge.
__global__ __launch_bounds__(256) void k_gpart() {
    int t = threadIdx.x;
    int j = blockIdx.x * 1024 + t * 4;
    int r0 = blockIdx.y * (NN / CHUNKS);     // 64 rows per chunk
    float m[4], s[4];
    #pragma unroll
    for (int c = 0; c < 4; c++) { m[c] = -1e30f; s[c] = 0.f; }

    const float* Cb = d_C + j;
    for (int rb = 0; rb < NN / CHUNKS; rb += 8) {
        float x[8][4];
        #pragma unroll
        for (int r = 0; r < 8; r++) {
            float fr = __ldg(&d_f[r0 + rb + r]);
            float4 cv = *(const float4*)(Cb + (size_t)(r0 + rb + r) * MM);
            x[r][0] = fmaf(cv.x, -INV_REG, fr);
            x[r][1] = fmaf(cv.y, -INV_REG, fr);
            x[r][2] = fmaf(cv.z, -INV_REG, fr);
            x[r][3] = fmaf(cv.w, -INV_REG, fr);
        }
        #pragma unroll
        for (int c = 0; c < 4; c++) {
            float bm = x[0][c];
            #pragma unroll
            for (int r = 1; r < 8; r++) bm = fmaxf(bm, x[r][c]);
            float nm = fmaxf(m[c], bm);
            float sc = s[c] * __expf(m[c] - nm);
            #pragma unroll
            for (int r = 0; r < 8; r++) sc += __expf(x[r][c] - nm);
            s[c] = sc;
            m[c] = nm;
        }
    }
    size_t o = (size_t)blockIdx.y * MM + j;
    *(float4*)(d_pm + o) = make_float4(m[0], m[1], m[2], m[3]);
    *(float4*)(d_ps + o) = make_float4(s[0], s[1], s[2], s[3]);
}

// ---------------- g update stage 2: combine partials ----------------
__global__ __launch_bounds__(256) void k_gcomb() {
    int j = blockIdx.x * 256 + threadIdx.x;
    float m = -1e30f, s = 0.f;
    #pragma unroll 8
    for (int c = 0; c < CHUNKS; c++)
        lse_merge(__ldg(&d_pm[(size_t)c * MM + j]), __ldg(&d_ps[(size_t)c * MM + j]), m, s);
    d_g[j] = d_logb[j] - (m + logf(s));
}

// ---------------- final OT loss: sum exp(f'+g'-C/reg) * C ----------------
__global__ __launch_bounds__(256) void k_ot() {
    int t = threadIdx.x;
    int j = blockIdx.x * 1024 + t * 4;
    int r0 = blockIdx.y * (NN / CHUNKS);
    float4 gv = *(const float4*)(d_g + j);
    float acc = 0.f;
    #pragma unroll 4
    for (int r = r0; r < r0 + (NN / CHUNKS); r++) {
        float fr = __ldg(&d_f[r]);
        float4 cv = *(const float4*)(d_C + (size_t)r * MM + j);
        acc += __expf(fmaf(cv.x, -INV_REG, fr + gv.x)) * cv.x;
        acc += __expf(fmaf(cv.y, -INV_REG, fr + gv.y)) * cv.y;
        acc += __expf(fmaf(cv.z, -INV_REG, fr + gv.z)) * cv.z;
        acc += __expf(fmaf(cv.w, -INV_REG, fr + gv.w)) * cv.w;
    }
    double da = (double)acc;
    #pragma unroll
    for (int o = 16; o; o >>= 1) da += __shfl_down_sync(0xffffffffu, da, o);
    __shared__ double sd[8];
    int lane = t & 31, w = t >> 5;
    if (lane == 0) sd[w] = da;
    __syncthreads();
    if (t == 0) {
        double tot = 0.0;
        #pragma unroll
        for (int k = 0; k < 8; k++) tot += sd[k];
        atomicAdd(&d_ot, tot);
    }
}

// ---------------- supervised alignment MSE ----------------
__global__ __launch_bounds__(128) void k_dist(const float* __restrict__ X,
                                              const float* __restrict__ W,
                                              const int* __restrict__ al) {
    int row = blockIdx.x, t = threadIdx.x;
    long long idx; int mask;
    if (d_is64) {
        long long v = ((const long long*)al)[row];
        mask = (v != -1LL);
        idx = v < 0 ? 0 : v;
    } else {
        int v = al[row];
        mask = (v != -1);
        idx = v < 0 ? 0 : (long long)v;
    }
    float4 a = ((const float4*)X)[(size_t)row * (DD / 4) + t];
    float4 b = ((const float4*)W)[(size_t)idx * (DD / 4) + t];
    float dx = a.x - b.x, dy = a.y - b.y, dz = a.z - b.z, dw = a.w - b.w;
    float s = dx * dx + dy * dy + dz * dz + dw * dw;
    #pragma unroll
    for (int o = 16; o; o >>= 1) s += __shfl_down_sync(0xffffffffu, s, o);
    __shared__ float red[4];
    if ((t & 31) == 0) red[t >> 5] = s;
    __syncthreads();
    if (t == 0) {
        float tot = red[0] + red[1] + red[2] + red[3];
        if (mask) {
            atomicAdd(&d_sq, (double)tot);
            atomicAdd(&d_cnt, 1.0);
        }
    }
}

// ---------------- finalize ----------------
__global__ void k_final(float* out) {
    double dl = (d_cnt > 0.0) ? d_sq / (d_cnt * (double)DD) : 0.0;
    out[0] = (float)(d_ot + dl);
}

// ---------------- launch ----------------
extern "C" void kernel_launch(void* const* d_in, const int* in_sizes, int n_in,
                              void* d_out, int out_size) {
    const float* X  = (const float*)d_in[0];   // descriptors   (4096, 512)
    const float* W  = (const float*)d_in[1];   // word_embeds   (8192, 512)
    const int*   AL = (const int*)d_in[2];     // aligned       (4096,) int32 or int64
    const float* T  = (const float*)d_in[3];   // tgt_probs     (8192,)
    float* out = (float*)d_out;

    k_init<<<1, 1024>>>(T, AL);
    k_sqnorm<<<NN, 128>>>(X, 0);
    k_sqnorm<<<MM, 128>>>(W, 1);
    dim3 gg(MM / 128, NN / 128);
    k_gemm<<<gg, 256>>>(X, W);

    for (int it = 0; it < N_ITERS; it++) {
        k_frow<<<NN / ROWS_PER_FBLK, 256>>>();
        k_gpart<<<dim3(MM / 1024, CHUNKS), 256>>>();
        k_gcomb<<<MM / 256, 256>>>();
    }

    k_ot<<<dim3(MM / 1024, CHUNKS), 256>>>();
    k_dist<<<NN, 128>>>(X, W, AL);
    k_final<<<1, 1>>>(out);
}

// round 3
// speedup vs baseline: 2.2755x; 1.3709x over previous
#include <cuda_runtime.h>
#include <math.h>

#define NN 4096
#define MM 8192
#define DD 512
#define INV_REG 10.0f
#define N_ITERS 200
#define LOGA   (-8.317766166719343f)   // -log(4096)
#define CHUNKS 64
#define ROWS_PER_FBLK 8
#define LN2F    0.69314718055994531f
#define LOG2EF  1.44269504088896340f

// ---------------- device scratch ----------------
__device__ __align__(16) float d_C[(size_t)NN * MM];            // fp32 cost (GEMM->quant only)
__device__ __align__(16) unsigned short d_Cq[(size_t)NN * MM];  // u16 quantized cost (64MB)
__device__ __align__(16) float d_f[NN];      // nat potentials
__device__ __align__(16) float d_g[MM];
__device__ __align__(16) float d_f2[NN];     // staged base-2 shifted potentials
__device__ __align__(16) float d_g2[MM];
__device__ __align__(16) float d_logb[MM];
__device__ __align__(16) float d_xsq[NN];
__device__ __align__(16) float d_ysq[MM];
__device__ __align__(16) float d_pm[(size_t)CHUNKS * MM];
__device__ __align__(16) float d_ps[(size_t)CHUNKS * MM];
__device__ double d_ot;
__device__ double d_sq;
__device__ double d_cnt;
__device__ int    d_is64;
__device__ unsigned int d_cminb, d_cmaxb;
__device__ float d_qK2, d_fgC, d_step, d_invstep, d_cmin, d_qdqB;

__device__ __forceinline__ float ex2(float x) {
    float r; asm("ex2.approx.ftz.f32 %0, %1;" : "=f"(r) : "f"(x)); return r;
}
__device__ __forceinline__ float lg2(float x) {
    float r; asm("lg2.approx.ftz.f32 %0, %1;" : "=f"(r) : "f"(x)); return r;
}
__device__ __forceinline__ void lse2_merge(float mo, float so, float& m, float& s) {
    float mn = fmaxf(m, mo);
    s = s * ex2(m - mn) + so * ex2(mo - mn);
    m = mn;
}
// u16 -> float(2^23 + q), one PRMT
__device__ __forceinline__ float qf_lo(unsigned w) {
    return __uint_as_float(__byte_perm(w, 0x4B000000u, 0x7410));
}
__device__ __forceinline__ float qf_hi(unsigned w) {
    return __uint_as_float(__byte_perm(w, 0x4B000000u, 0x7432));
}

// ---------------- init ----------------
__global__ void k_init(const float* __restrict__ tgt, const int* __restrict__ al_raw) {
    __shared__ float red[32];
    __shared__ float s_total;
    int t = threadIdx.x;
    float s = 0.f;
    for (int j = t; j < MM; j += 1024) s += tgt[j];
    #pragma unroll
    for (int o = 16; o; o >>= 1) s += __shfl_down_sync(0xffffffffu, s, o);
    if ((t & 31) == 0) red[t >> 5] = s;
    __syncthreads();
    if (t < 32) {
        float v = red[t];
        #pragma unroll
        for (int o = 16; o; o >>= 1) v += __shfl_down_sync(0xffffffffu, v, o);
        if (t == 0) s_total = v;
    }
    __syncthreads();
    float lt = logf(s_total);
    for (int j = t; j < MM; j += 1024) {
        d_logb[j] = logf(tgt[j]) - lt;
        d_g[j] = 0.f;
    }
    int odd_nz = 0;
    for (int i = t; i < NN / 2; i += 1024)
        if (al_raw[2 * i + 1] != 0) odd_nz = 1;
    odd_nz = __syncthreads_or(odd_nz);
    if (t == 0) {
        d_is64 = odd_nz ? 0 : 1;
        d_ot = 0.0; d_sq = 0.0; d_cnt = 0.0;
        d_cminb = 0x7F7FFFFFu;   // FLT_MAX (C >= 0, uint order == float order)
        d_cmaxb = 0u;
    }
}

// ---------------- row squared norms ----------------
__global__ __launch_bounds__(128) void k_sqnorm(const float* __restrict__ X, int which) {
    int row = blockIdx.x, t = threadIdx.x;
    float4 v = ((const float4*)X)[(size_t)row * (DD / 4) + t];
    float s = v.x * v.x + v.y * v.y + v.z * v.z + v.w * v.w;
    #pragma unroll
    for (int o = 16; o; o >>= 1) s += __shfl_down_sync(0xffffffffu, s, o);
    __shared__ float red[4];
    if ((t & 31) == 0) red[t >> 5] = s;
    __syncthreads();
    if (t == 0) {
        float tot = red[0] + red[1] + red[2] + red[3];
        if (which == 0) d_xsq[row] = tot; else d_ysq[row] = tot;
    }
}

// ---------------- GEMM + cdist epilogue + global min/max ----------------
__global__ __launch_bounds__(256) void k_gemm(const float* __restrict__ X, const float* __restrict__ Y) {
    __shared__ float As[16][128];
    __shared__ float Bs[16][128];
    int tid = threadIdx.x;
    int bx = blockIdx.x, by = blockIdx.y;
    int tx = tid & 15, ty = tid >> 4;
    float acc[8][8];
    #pragma unroll
    for (int i = 0; i < 8; i++)
        #pragma unroll
        for (int j = 0; j < 8; j++) acc[i][j] = 0.f;

    const float* Xb = X + (size_t)by * 128 * DD;
    const float* Yb = Y + (size_t)bx * 128 * DD;

    for (int kt = 0; kt < DD; kt += 16) {
        __syncthreads();
        #pragma unroll
        for (int i = 0; i < 2; i++) {
            int l  = tid + i * 256;
            int r  = l >> 2;
            int c4 = l & 3;
            float4 va = *(const float4*)(Xb + (size_t)r * DD + kt + c4 * 4);
            As[c4 * 4 + 0][r] = va.x; As[c4 * 4 + 1][r] = va.y;
            As[c4 * 4 + 2][r] = va.z; As[c4 * 4 + 3][r] = va.w;
            float4 vb = *(const float4*)(Yb + (size_t)r * DD + kt + c4 * 4);
            Bs[c4 * 4 + 0][r] = vb.x; Bs[c4 * 4 + 1][r] = vb.y;
            Bs[c4 * 4 + 2][r] = vb.z; Bs[c4 * 4 + 3][r] = vb.w;
        }
        __syncthreads();
        #pragma unroll
        for (int kk = 0; kk < 16; kk++) {
            float a[8], b[8];
            *(float4*)(a)     = *(const float4*)&As[kk][ty * 8];
            *(float4*)(a + 4) = *(const float4*)&As[kk][ty * 8 + 4];
            *(float4*)(b)     = *(const float4*)&Bs[kk][tx * 8];
            *(float4*)(b + 4) = *(const float4*)&Bs[kk][tx * 8 + 4];
            #pragma unroll
            for (int i = 0; i < 8; i++)
                #pragma unroll
                for (int j = 0; j < 8; j++)
                    acc[i][j] = fmaf(a[i], b[j], acc[i][j]);
        }
    }
    int i0 = by * 128 + ty * 8;
    int j0 = bx * 128 + tx * 8;
    float ys[8];
    #pragma unroll
    for (int jj = 0; jj < 8; jj++) ys[jj] = d_ysq[j0 + jj];
    float tmin = 3.4e38f, tmax = 0.f;
    #pragma unroll
    for (int ii = 0; ii < 8; ii++) {
        float xs = d_xsq[i0 + ii];
        float o[8];
        #pragma unroll
        for (int jj = 0; jj < 8; jj++) {
            float sq = xs + ys[jj] - 2.0f * acc[ii][jj];
            o[jj] = sqrtf(fmaxf(sq, 1e-12f));
            tmin = fminf(tmin, o[jj]);
            tmax = fmaxf(tmax, o[jj]);
        }
        float4* dst = (float4*)(d_C + (size_t)(i0 + ii) * MM + j0);
        dst[0] = make_float4(o[0], o[1], o[2], o[3]);
        dst[1] = make_float4(o[4], o[5], o[6], o[7]);
    }
    // block min/max -> global atomics
    #pragma unroll
    for (int o = 16; o; o >>= 1) {
        tmin = fminf(tmin, __shfl_xor_sync(0xffffffffu, tmin, o));
        tmax = fmaxf(tmax, __shfl_xor_sync(0xffffffffu, tmax, o));
    }
    __shared__ float rmin[8], rmax[8];
    int lane = tid & 31, w = tid >> 5;
    if (lane == 0) { rmin[w] = tmin; rmax[w] = tmax; }
    __syncthreads();
    if (tid == 0) {
        float bm = rmin[0], bM = rmax[0];
        #pragma unroll
        for (int k = 1; k < 8; k++) { bm = fminf(bm, rmin[k]); bM = fmaxf(bM, rmax[k]); }
        atomicMin(&d_cminb, __float_as_uint(bm));
        atomicMax(&d_cmaxb, __float_as_uint(bM));
    }
}

// ---------------- derive quantizer constants ----------------
__global__ void k_scale() {
    float cmin = __uint_as_float(d_cminb);
    float cmax = __uint_as_float(d_cmaxb);
    double w = (double)cmax - (double)cmin;
    if (w < 1e-9) w = 1e-9;
    double st = w / 65535.0;
    const double L2E = 1.4426950408889634;
    float K2f = (float)(10.0 * st * L2E);
    double C0 = 8388608.0 * (double)K2f;     // 2^23 * K2 (fold for magic-number dequant)
    d_step = (float)st;
    d_invstep = (float)(1.0 / st);
    d_cmin = cmin;
    d_qK2 = K2f;
    d_fgC = (float)(-10.0 * (double)cmin * L2E + C0);
    d_qdqB = (float)((double)cmin - 8388608.0 * st);
}

// ---------------- quantize C fp32 -> u16 ----------------
__global__ __launch_bounds__(256) void k_quant() {
    size_t i = (size_t)blockIdx.x * 256 + threadIdx.x;   // handles 8 elems
    float inv = d_invstep, cmin = d_cmin;
    float4 a = ((const float4*)d_C)[i * 2];
    float4 b = ((const float4*)d_C)[i * 2 + 1];
    unsigned q[8];
    float v[8] = {a.x, a.y, a.z, a.w, b.x, b.y, b.z, b.w};
    #pragma unroll
    for (int k = 0; k < 8; k++) {
        unsigned qq = __float2uint_rn((v[k] - cmin) * inv);
        q[k] = qq > 65535u ? 65535u : qq;
    }
    uint4 o;
    o.x = __byte_perm(q[0], q[1], 0x5410);
    o.y = __byte_perm(q[2], q[3], 0x5410);
    o.z = __byte_perm(q[4], q[5], 0x5410);
    o.w = __byte_perm(q[6], q[7], 0x5410);
    ((uint4*)d_Cq)[i] = o;
}

// ---------------- g2 init (g=0) ----------------
__global__ void k_ginit() {
    d_g2[blockIdx.x * 256 + threadIdx.x] = d_fgC;
}

// ---------------- f update: row LSE over u16 C ----------------
__global__ __launch_bounds__(256) void k_frow() {
    __shared__ float sg[MM];          // staged d_g2 (32 KB)
    __shared__ float red_m[8], red_s[8];
    int t = threadIdx.x, lane = t & 31, w = t >> 5;
    float K2 = d_qK2;
    float fgC = d_fgC;
    #pragma unroll
    for (int k = 0; k < 8; k++)
        ((float4*)sg)[t + k * 256] = ((const float4*)d_g2)[t + k * 256];
    __syncthreads();

    int row0 = blockIdx.x * ROWS_PER_FBLK;
    for (int rr = 0; rr < ROWS_PER_FBLK; rr++) {
        int row = row0 + rr;
        const uint4* C4 = (const uint4*)(d_Cq + (size_t)row * MM);
        float x[32];
        #pragma unroll
        for (int k = 0; k < 4; k++) {
            uint4 v = C4[t + k * 256];
            const float* sgp = sg + (t + k * 256) * 8;
            unsigned wd[4] = {v.x, v.y, v.z, v.w};
            #pragma unroll
            for (int p = 0; p < 4; p++) {
                x[k * 8 + p * 2 + 0] = fmaf(qf_lo(wd[p]), -K2, sgp[p * 2 + 0]);
                x[k * 8 + p * 2 + 1] = fmaf(qf_hi(wd[p]), -K2, sgp[p * 2 + 1]);
            }
        }
        float m = x[0];
        #pragma unroll
        for (int i = 1; i < 32; i++) m = fmaxf(m, x[i]);
        #pragma unroll
        for (int o = 16; o; o >>= 1) m = fmaxf(m, __shfl_xor_sync(0xffffffffu, m, o));
        float s0 = 0.f, s1 = 0.f, s2 = 0.f, s3 = 0.f;
        #pragma unroll
        for (int i = 0; i < 32; i += 4) {
            s0 += ex2(x[i + 0] - m);
            s1 += ex2(x[i + 1] - m);
            s2 += ex2(x[i + 2] - m);
            s3 += ex2(x[i + 3] - m);
        }
        float s = (s0 + s1) + (s2 + s3);
        #pragma unroll
        for (int o = 16; o; o >>= 1) s += __shfl_down_sync(0xffffffffu, s, o);
        if (lane == 0) { red_m[w] = m; red_s[w] = s; }
        __syncthreads();
        if (t == 0) {
            float fm = red_m[0], fs = red_s[0];
            #pragma unroll
            for (int k = 1; k < 8; k++) lse2_merge(red_m[k], red_s[k], fm, fs);
            float f = LOGA - LN2F * (fm + lg2(fs));
            d_f[row] = f;
            d_f2[row] = fmaf(f, LOG2EF, fgC);
        }
        __syncthreads();
    }
}

// ---------------- g update stage 1: column LSE partials over u16 C ----------------
__global__ __launch_bounds__(256) void k_gpart() {
    int t = threadIdx.x;
    int j = blockIdx.x * 1024 + t * 4;       // 4 cols/thread, grid.x = 8
    int r0 = blockIdx.y * (NN / CHUNKS);     // 64 rows per chunk
    float K2 = d_qK2;
    float m[4], s[4];
    #pragma unroll
    for (int c = 0; c < 4; c++) { m[c] = -1e30f; s[c] = 0.f; }

    const unsigned short* Cb = d_Cq + j;
    for (int rb = 0; rb < NN / CHUNKS; rb += 8) {
        float x[8][4];
        #pragma unroll
        for (int r = 0; r < 8; r++) {
            int rr = r0 + rb + r;
            float F2 = __ldg(&d_f2[rr]);
            uint2 v = *(const uint2*)(Cb + (size_t)rr * MM);
            x[r][0] = fmaf(qf_lo(v.x), -K2, F2);
            x[r][1] = fmaf(qf_hi(v.x), -K2, F2);
            x[r][2] = fmaf(qf_lo(v.y), -K2, F2);
            x[r][3] = fmaf(qf_hi(v.y), -K2, F2);
        }
        #pragma unroll
        for (int c = 0; c < 4; c++) {
            float bm = x[0][c];
            #pragma unroll
            for (int r = 1; r < 8; r++) bm = fmaxf(bm, x[r][c]);
            float nm = fmaxf(m[c], bm);
            float sc = s[c] * ex2(m[c] - nm);
            #pragma unroll
            for (int r = 0; r < 8; r++) sc += ex2(x[r][c] - nm);
            s[c] = sc;
            m[c] = nm;
        }
    }
    size_t o = (size_t)blockIdx.y * MM + j;
    *(float4*)(d_pm + o) = make_float4(m[0], m[1], m[2], m[3]);
    *(float4*)(d_ps + o) = make_float4(s[0], s[1], s[2], s[3]);
}

// ---------------- g update stage 2: combine ----------------
__global__ __launch_bounds__(256) void k_gcomb() {
    int j = blockIdx.x * 256 + threadIdx.x;
    float m = -1e30f, s = 0.f;
    #pragma unroll 8
    for (int c = 0; c < CHUNKS; c++)
        lse2_merge(__ldg(&d_pm[(size_t)c * MM + j]), __ldg(&d_ps[(size_t)c * MM + j]), m, s);
    float g = d_logb[j] - LN2F * (m + lg2(s));
    d_g[j] = g;
    d_g2[j] = fmaf(g, LOG2EF, d_fgC);
}

// ---------------- final OT loss: sum exp(f+g-10C)*C  (u16 C) ----------------
__global__ __launch_bounds__(256) void k_ot() {
    int t = threadIdx.x;
    int j = blockIdx.x * 1024 + t * 4;
    int r0 = blockIdx.y * (NN / CHUNKS);
    float K2 = d_qK2, stepf = d_step, qB = d_qdqB, fgC = d_fgC;
    float4 gv = *(const float4*)(d_g + j);
    float base[4];
    base[0] = fmaf(gv.x, LOG2EF, fgC);
    base[1] = fmaf(gv.y, LOG2EF, fgC);
    base[2] = fmaf(gv.z, LOG2EF, fgC);
    base[3] = fmaf(gv.w, LOG2EF, fgC);
    const unsigned short* Cb = d_Cq + j;
    float acc = 0.f;
    for (int r = r0; r < r0 + (NN / CHUNKS); r++) {
        float frl2 = __ldg(&d_f[r]) * LOG2EF;
        uint2 v = *(const uint2*)(Cb + (size_t)r * MM);
        float qf[4] = {qf_lo(v.x), qf_hi(v.x), qf_lo(v.y), qf_hi(v.y)};
        #pragma unroll
        for (int c = 0; c < 4; c++) {
            float p = ex2(fmaf(qf[c], -K2, base[c] + frl2));
            float cd = fmaf(qf[c], stepf, qB);
            acc = fmaf(p, cd, acc);
        }
    }
    double da = (double)acc;
    #pragma unroll
    for (int o = 16; o; o >>= 1) da += __shfl_down_sync(0xffffffffu, da, o);
    __shared__ double sd[8];
    int lane = t & 31, w = t >> 5;
    if (lane == 0) sd[w] = da;
    __syncthreads();
    if (t == 0) {
        double tot = 0.0;
        #pragma unroll
        for (int k = 0; k < 8; k++) tot += sd[k];
        atomicAdd(&d_ot, tot);
    }
}

// ---------------- supervised alignment MSE ----------------
__global__ __launch_bounds__(128) void k_dist(const float* __restrict__ X,
                                              const float* __restrict__ W,
                                              const int* __restrict__ al) {
    int row = blockIdx.x, t = threadIdx.x;
    long long idx; int mask;
    if (d_is64) {
        long long v = ((const long long*)al)[row];
        mask = (v != -1LL);
        idx = v < 0 ? 0 : v;
    } else {
        int v = al[row];
        mask = (v != -1);
        idx = v < 0 ? 0 : (long long)v;
    }
    float4 a = ((const float4*)X)[(size_t)row * (DD / 4) + t];
    float4 b = ((const float4*)W)[(size_t)idx * (DD / 4) + t];
    float dx = a.x - b.x, dy = a.y - b.y, dz = a.z - b.z, dw = a.w - b.w;
    float s = dx * dx + dy * dy + dz * dz + dw * dw;
    #pragma unroll
    for (int o = 16; o; o >>= 1) s += __shfl_down_sync(0xffffffffu, s, o);
    __shared__ float red[4];
    if ((t & 31) == 0) red[t >> 5] = s;
    __syncthreads();
    if (t == 0) {
        float tot = red[0] + red[1] + red[2] + red[3];
        if (mask) {
            atomicAdd(&d_sq, (double)tot);
            atomicAdd(&d_cnt, 1.0);
        }
    }
}

// ---------------- finalize ----------------
__global__ void k_final(float* out) {
    double dl = (d_cnt > 0.0) ? d_sq / (d_cnt * (double)DD) : 0.0;
    out[0] = (float)(d_ot + dl);
}

// ---------------- launch ----------------
extern "C" void kernel_launch(void* const* d_in, const int* in_sizes, int n_in,
                              void* d_out, int out_size) {
    const float* X  = (const float*)d_in[0];
    const float* W  = (const float*)d_in[1];
    const int*   AL = (const int*)d_in[2];
    const float* T  = (const float*)d_in[3];
    float* out = (float*)d_out;

    k_init<<<1, 1024>>>(T, AL);
    k_sqnorm<<<NN, 128>>>(X, 0);
    k_sqnorm<<<MM, 128>>>(W, 1);
    dim3 gg(MM / 128, NN / 128);
    k_gemm<<<gg, 256>>>(X, W);
    k_scale<<<1, 1>>>();
    k_quant<<<(int)(((size_t)NN * MM) / (256 * 8)), 256>>>();
    k_ginit<<<MM / 256, 256>>>();

    for (int it = 0; it < N_ITERS; it++) {
        k_frow<<<NN / ROWS_PER_FBLK, 256>>>();
        k_gpart<<<dim3(8, CHUNKS), 256>>>();
        k_gcomb<<<MM / 256, 256>>>();
    }

    k_ot<<<dim3(8, CHUNKS), 256>>>();
    k_dist<<<NN, 128>>>(X, W, AL);
    k_final<<<1, 1>>>(out);
}

// round 4
// speedup vs baseline: 2.8011x; 1.2310x over previous
#include <cuda_runtime.h>
#include <math.h>

#define NN 4096
#define MM 8192
#define DD 512
#define N_ITERS 200
#define LOGA   (-8.317766166719343f)   // -log(4096)
#define CHUNKS 64
#define FROWS 8
#define LN2F    0.69314718055994531f
#define LOG2EF  1.44269504088896340f

// ---------------- device scratch ----------------
__device__ __align__(16) unsigned short d_Cq[(size_t)NN * MM];  // u16 quantized cost (64MB)
__device__ __align__(16) float d_f[NN];      // nat potentials
__device__ __align__(16) float d_g[MM];
__device__ __align__(16) float d_f2[NN];     // staged base-2 shifted potentials
__device__ __align__(16) float d_g2[MM];
__device__ __align__(16) float d_logb[MM];
__device__ __align__(16) float d_xsq[NN];
__device__ __align__(16) float d_ysq[MM];
__device__ __align__(16) float d_pm[(size_t)CHUNKS * MM];
__device__ __align__(16) float d_ps[(size_t)CHUNKS * MM];
__device__ double d_ot;
__device__ double d_sq;
__device__ double d_cnt;
__device__ int    d_is64;
__device__ float d_qK2, d_fgC, d_step, d_invstep, d_qdqB;

__device__ __forceinline__ float ex2(float x) {
    float r; asm("ex2.approx.ftz.f32 %0, %1;" : "=f"(r) : "f"(x)); return r;
}
__device__ __forceinline__ float lg2(float x) {
    float r; asm("lg2.approx.ftz.f32 %0, %1;" : "=f"(r) : "f"(x)); return r;
}
__device__ __forceinline__ void lse2_merge(float mo, float so, float& m, float& s) {
    float mn = fmaxf(m, mo);
    s = s * ex2(m - mn) + so * ex2(mo - mn);
    m = mn;
}
// u16 -> float(2^23 + q), one PRMT
__device__ __forceinline__ float qf_lo(unsigned w) {
    return __uint_as_float(__byte_perm(w, 0x4B000000u, 0x7410));
}
__device__ __forceinline__ float qf_hi(unsigned w) {
    return __uint_as_float(__byte_perm(w, 0x4B000000u, 0x7432));
}

// ---------------- init ----------------
__global__ void k_init(const float* __restrict__ tgt, const int* __restrict__ al_raw) {
    __shared__ float red[32];
    __shared__ float s_total;
    int t = threadIdx.x;
    float s = 0.f;
    for (int j = t; j < MM; j += 1024) s += tgt[j];
    #pragma unroll
    for (int o = 16; o; o >>= 1) s += __shfl_down_sync(0xffffffffu, s, o);
    if ((t & 31) == 0) red[t >> 5] = s;
    __syncthreads();
    if (t < 32) {
        float v = red[t];
        #pragma unroll
        for (int o = 16; o; o >>= 1) v += __shfl_down_sync(0xffffffffu, v, o);
        if (t == 0) s_total = v;
    }
    __syncthreads();
    float lt = logf(s_total);
    for (int j = t; j < MM; j += 1024) {
        d_logb[j] = logf(tgt[j]) - lt;
        d_g[j] = 0.f;
    }
    int odd_nz = 0;
    for (int i = t; i < NN / 2; i += 1024)
        if (al_raw[2 * i + 1] != 0) odd_nz = 1;
    odd_nz = __syncthreads_or(odd_nz);
    if (t == 0) {
        d_is64 = odd_nz ? 0 : 1;
        d_ot = 0.0; d_sq = 0.0; d_cnt = 0.0;
    }
}

// ---------------- row squared norms ----------------
__global__ __launch_bounds__(128) void k_sqnorm(const float* __restrict__ X, int which) {
    int row = blockIdx.x, t = threadIdx.x;
    float4 v = ((const float4*)X)[(size_t)row * (DD / 4) + t];
    float s = v.x * v.x + v.y * v.y + v.z * v.z + v.w * v.w;
    #pragma unroll
    for (int o = 16; o; o >>= 1) s += __shfl_down_sync(0xffffffffu, s, o);
    __shared__ float red[4];
    if ((t & 31) == 0) red[t >> 5] = s;
    __syncthreads();
    if (t == 0) {
        float tot = red[0] + red[1] + red[2] + red[3];
        if (which == 0) d_xsq[row] = tot; else d_ysq[row] = tot;
    }
}

// ---------------- quantizer constants from norm bounds (C in [0, B]) ----------------
__global__ void k_scale() {
    __shared__ float red[32];
    int t = threadIdx.x;               // 1024 threads, 1 block
    float mx = 0.f;
    for (int i = t; i < NN; i += 1024) mx = fmaxf(mx, d_xsq[i]);
    #pragma unroll
    for (int o = 16; o; o >>= 1) mx = fmaxf(mx, __shfl_xor_sync(0xffffffffu, mx, o));
    if ((t & 31) == 0) red[t >> 5] = mx;
    __syncthreads();
    float my = 0.f;
    for (int i = t; i < MM; i += 1024) my = fmaxf(my, d_ysq[i]);
    #pragma unroll
    for (int o = 16; o; o >>= 1) my = fmaxf(my, __shfl_xor_sync(0xffffffffu, my, o));
    __shared__ float red2[32];
    if ((t & 31) == 0) red2[t >> 5] = my;
    __syncthreads();
    if (t == 0) {
        float MX = 0.f, MY = 0.f;
        #pragma unroll
        for (int k = 0; k < 32; k++) { MX = fmaxf(MX, red[k]); MY = fmaxf(MY, red2[k]); }
        double B = 1.02 * ((double)sqrtf(MX) + (double)sqrtf(MY)) + 1e-3;
        double st = B / 65535.0;
        const double L2E = 1.4426950408889634;
        float K2f = (float)(10.0 * st * L2E);
        d_step = (float)st;
        d_invstep = (float)(1.0 / st);
        d_qK2 = K2f;
        d_fgC = (float)(8388608.0 * (double)K2f);   // 2^23*K2 fold for magic dequant
        d_qdqB = (float)(-8388608.0 * st);
    }
}

// ---------------- GEMM + cdist epilogue, writes u16 directly ----------------
__global__ __launch_bounds__(256) void k_gemm(const float* __restrict__ X, const float* __restrict__ Y) {
    __shared__ float As[16][128];
    __shared__ float Bs[16][128];
    int tid = threadIdx.x;
    int bx = blockIdx.x, by = blockIdx.y;
    int tx = tid & 15, ty = tid >> 4;
    float acc[8][8];
    #pragma unroll
    for (int i = 0; i < 8; i++)
        #pragma unroll
        for (int j = 0; j < 8; j++) acc[i][j] = 0.f;

    const float* Xb = X + (size_t)by * 128 * DD;
    const float* Yb = Y + (size_t)bx * 128 * DD;

    for (int kt = 0; kt < DD; kt += 16) {
        __syncthreads();
        #pragma unroll
        for (int i = 0; i < 2; i++) {
            int l  = tid + i * 256;
            int r  = l >> 2;
            int c4 = l & 3;
            float4 va = *(const float4*)(Xb + (size_t)r * DD + kt + c4 * 4);
            As[c4 * 4 + 0][r] = va.x; As[c4 * 4 + 1][r] = va.y;
            As[c4 * 4 + 2][r] = va.z; As[c4 * 4 + 3][r] = va.w;
            float4 vb = *(const float4*)(Yb + (size_t)r * DD + kt + c4 * 4);
            Bs[c4 * 4 + 0][r] = vb.x; Bs[c4 * 4 + 1][r] = vb.y;
            Bs[c4 * 4 + 2][r] = vb.z; Bs[c4 * 4 + 3][r] = vb.w;
        }
        __syncthreads();
        #pragma unroll
        for (int kk = 0; kk < 16; kk++) {
            float a[8], b[8];
            *(float4*)(a)     = *(const float4*)&As[kk][ty * 8];
            *(float4*)(a + 4) = *(const float4*)&As[kk][ty * 8 + 4];
            *(float4*)(b)     = *(const float4*)&Bs[kk][tx * 8];
            *(float4*)(b + 4) = *(const float4*)&Bs[kk][tx * 8 + 4];
            #pragma unroll
            for (int i = 0; i < 8; i++)
                #pragma unroll
                for (int j = 0; j < 8; j++)
                    acc[i][j] = fmaf(a[i], b[j], acc[i][j]);
        }
    }
    int i0 = by * 128 + ty * 8;
    int j0 = bx * 128 + tx * 8;
    float inv = d_invstep;
    float ys[8];
    #pragma unroll
    for (int jj = 0; jj < 8; jj++) ys[jj] = d_ysq[j0 + jj];
    #pragma unroll
    for (int ii = 0; ii < 8; ii++) {
        float xs = d_xsq[i0 + ii];
        unsigned q[8];
        #pragma unroll
        for (int jj = 0; jj < 8; jj++) {
            float sq = xs + ys[jj] - 2.0f * acc[ii][jj];
            float c = sqrtf(fmaxf(sq, 1e-12f));
            unsigned qq = __float2uint_rn(c * inv);
            q[jj] = qq > 65535u ? 65535u : qq;
        }
        uint4 o;
        o.x = __byte_perm(q[0], q[1], 0x5410);
        o.y = __byte_perm(q[2], q[3], 0x5410);
        o.z = __byte_perm(q[4], q[5], 0x5410);
        o.w = __byte_perm(q[6], q[7], 0x5410);
        *(uint4*)(d_Cq + (size_t)(i0 + ii) * MM + j0) = o;
    }
}

// ---------------- g2 init (g=0) ----------------
__global__ void k_ginit() {
    d_g2[blockIdx.x * 256 + threadIdx.x] = d_fgC;
}

// ---------------- f update: row LSE, g2 in registers, fixed-shift reductions ----------------
__global__ __launch_bounds__(256) void k_frow() {
    int t = threadIdx.x;
    int lane = t & 31, w = t >> 5;
    float K2 = d_qK2, fgC = d_fgC;
    int row0 = blockIdx.x * FROWS;

    // this thread's 32 g2 values (columns {(s*256+t)*8 + e})
    float g2r[32];
    #pragma unroll
    for (int s = 0; s < 4; s++) {
        float4 a = *(const float4*)(d_g2 + (size_t)(s * 256 + t) * 8);
        float4 b = *(const float4*)(d_g2 + (size_t)(s * 256 + t) * 8 + 4);
        g2r[s * 8 + 0] = a.x; g2r[s * 8 + 1] = a.y; g2r[s * 8 + 2] = a.z; g2r[s * 8 + 3] = a.w;
        g2r[s * 8 + 4] = b.x; g2r[s * 8 + 5] = b.y; g2r[s * 8 + 6] = b.z; g2r[s * 8 + 7] = b.w;
    }

    float rm[FROWS], rs[FROWS];
    #pragma unroll
    for (int rr = 0; rr < FROWS; rr++) {
        const uint4* Crow = (const uint4*)(d_Cq + (size_t)(row0 + rr) * MM);
        float x[32];
        #pragma unroll
        for (int s = 0; s < 4; s++) {
            uint4 cv = Crow[s * 256 + t];
            x[s * 8 + 0] = fmaf(qf_lo(cv.x), -K2, g2r[s * 8 + 0]);
            x[s * 8 + 1] = fmaf(qf_hi(cv.x), -K2, g2r[s * 8 + 1]);
            x[s * 8 + 2] = fmaf(qf_lo(cv.y), -K2, g2r[s * 8 + 2]);
            x[s * 8 + 3] = fmaf(qf_hi(cv.y), -K2, g2r[s * 8 + 3]);
            x[s * 8 + 4] = fmaf(qf_lo(cv.z), -K2, g2r[s * 8 + 4]);
            x[s * 8 + 5] = fmaf(qf_hi(cv.z), -K2, g2r[s * 8 + 5]);
            x[s * 8 + 6] = fmaf(qf_lo(cv.w), -K2, g2r[s * 8 + 6]);
            x[s * 8 + 7] = fmaf(qf_hi(cv.w), -K2, g2r[s * 8 + 7]);
        }
        float m = x[0];
        #pragma unroll
        for (int i = 1; i < 32; i++) m = fmaxf(m, x[i]);
        float s0 = 0.f, s1 = 0.f, s2 = 0.f, s3 = 0.f;
        #pragma unroll
        for (int i = 0; i < 32; i += 4) {
            s0 += ex2(x[i + 0] - m);
            s1 += ex2(x[i + 1] - m);
            s2 += ex2(x[i + 2] - m);
            s3 += ex2(x[i + 3] - m);
        }
        rm[rr] = m;
        rs[rr] = (s0 + s1) + (s2 + s3);
    }

    // per-warp fixed-shift reduce for each row -> smem
    __shared__ float sm[FROWS][8], ss[FROWS][8];
    #pragma unroll
    for (int rr = 0; rr < FROWS; rr++) {
        float m = rm[rr], s = rs[rr];
        float M = m;
        #pragma unroll
        for (int o = 16; o; o >>= 1) M = fmaxf(M, __shfl_xor_sync(0xffffffffu, M, o));
        s *= ex2(m - M);
        #pragma unroll
        for (int o = 16; o; o >>= 1) s += __shfl_xor_sync(0xffffffffu, s, o);
        if (lane == 0) { sm[rr][w] = M; ss[rr][w] = s; }
    }
    __syncthreads();
    // warp w finalizes row w (8 partials)
    {
        float M = (lane < 8) ? sm[w][lane] : -1e30f;
        float S = (lane < 8) ? ss[w][lane] : 0.f;
        float Mf = M;
        #pragma unroll
        for (int o = 4; o; o >>= 1) Mf = fmaxf(Mf, __shfl_xor_sync(0xffffffffu, Mf, o));
        S *= ex2(M - Mf);
        #pragma unroll
        for (int o = 4; o; o >>= 1) S += __shfl_xor_sync(0xffffffffu, S, o);
        if (lane == 0) {
            float f = LOGA - LN2F * (Mf + lg2(S));
            d_f[row0 + w] = f;
            d_f2[row0 + w] = fmaf(f, LOG2EF, fgC);
        }
    }
}

// ---------------- g update stage 1: column LSE partials ----------------
__global__ __launch_bounds__(256) void k_gpart() {
    int t = threadIdx.x;
    int j = blockIdx.x * 1024 + t * 4;
    int r0 = blockIdx.y * (NN / CHUNKS);
    float K2 = d_qK2;
    float m[4], s[4];
    #pragma unroll
    for (int c = 0; c < 4; c++) { m[c] = -1e30f; s[c] = 0.f; }

    const unsigned short* Cb = d_Cq + j;
    for (int rb = 0; rb < NN / CHUNKS; rb += 8) {
        float x[8][4];
        #pragma unroll
        for (int r = 0; r < 8; r++) {
            int rr = r0 + rb + r;
            float F2 = __ldg(&d_f2[rr]);
            uint2 v = *(const uint2*)(Cb + (size_t)rr * MM);
            x[r][0] = fmaf(qf_lo(v.x), -K2, F2);
            x[r][1] = fmaf(qf_hi(v.x), -K2, F2);
            x[r][2] = fmaf(qf_lo(v.y), -K2, F2);
            x[r][3] = fmaf(qf_hi(v.y), -K2, F2);
        }
        #pragma unroll
        for (int c = 0; c < 4; c++) {
            float bm = x[0][c];
            #pragma unroll
            for (int r = 1; r < 8; r++) bm = fmaxf(bm, x[r][c]);
            float nm = fmaxf(m[c], bm);
            float sc = s[c] * ex2(m[c] - nm);
            #pragma unroll
            for (int r = 0; r < 8; r++) sc += ex2(x[r][c] - nm);
            s[c] = sc;
            m[c] = nm;
        }
    }
    size_t o = (size_t)blockIdx.y * MM + j;
    *(float4*)(d_pm + o) = make_float4(m[0], m[1], m[2], m[3]);
    *(float4*)(d_ps + o) = make_float4(s[0], s[1], s[2], s[3]);
}

// ---------------- g update stage 2: combine ----------------
__global__ __launch_bounds__(256) void k_gcomb() {
    int j = blockIdx.x * 256 + threadIdx.x;
    float m = -1e30f, s = 0.f;
    #pragma unroll 8
    for (int c = 0; c < CHUNKS; c++)
        lse2_merge(__ldg(&d_pm[(size_t)c * MM + j]), __ldg(&d_ps[(size_t)c * MM + j]), m, s);
    float g = d_logb[j] - LN2F * (m + lg2(s));
    d_g[j] = g;
    d_g2[j] = fmaf(g, LOG2EF, d_fgC);
}

// ---------------- final OT loss ----------------
__global__ __launch_bounds__(256) void k_ot() {
    int t = threadIdx.x;
    int j = blockIdx.x * 1024 + t * 4;
    int r0 = blockIdx.y * (NN / CHUNKS);
    float K2 = d_qK2, stepf = d_step, qB = d_qdqB, fgC = d_fgC;
    float4 gv = *(const float4*)(d_g + j);
    float base[4];
    base[0] = fmaf(gv.x, LOG2EF, fgC);
    base[1] = fmaf(gv.y, LOG2EF, fgC);
    base[2] = fmaf(gv.z, LOG2EF, fgC);
    base[3] = fmaf(gv.w, LOG2EF, fgC);
    const unsigned short* Cb = d_Cq + j;
    float acc = 0.f;
    for (int r = r0; r < r0 + (NN / CHUNKS); r++) {
        float frl2 = __ldg(&d_f[r]) * LOG2EF;
        uint2 v = *(const uint2*)(Cb + (size_t)r * MM);
        float qf[4] = {qf_lo(v.x), qf_hi(v.x), qf_lo(v.y), qf_hi(v.y)};
        #pragma unroll
        for (int c = 0; c < 4; c++) {
            float p = ex2(fmaf(qf[c], -K2, base[c] + frl2));
            float cd = fmaf(qf[c], stepf, qB);
            acc = fmaf(p, cd, acc);
        }
    }
    double da = (double)acc;
    #pragma unroll
    for (int o = 16; o; o >>= 1) da += __shfl_down_sync(0xffffffffu, da, o);
    __shared__ double sd[8];
    int lane = t & 31, w = t >> 5;
    if (lane == 0) sd[w] = da;
    __syncthreads();
    if (t == 0) {
        double tot = 0.0;
        #pragma unroll
        for (int k = 0; k < 8; k++) tot += sd[k];
        atomicAdd(&d_ot, tot);
    }
}

// ---------------- supervised alignment MSE ----------------
__global__ __launch_bounds__(128) void k_dist(const float* __restrict__ X,
                                              const float* __restrict__ W,
                                              const int* __restrict__ al) {
    int row = blockIdx.x, t = threadIdx.x;
    long long idx; int mask;
    if (d_is64) {
        long long v = ((const long long*)al)[row];
        mask = (v != -1LL);
        idx = v < 0 ? 0 : v;
    } else {
        int v = al[row];
        mask = (v != -1);
        idx = v < 0 ? 0 : (long long)v;
    }
    float4 a = ((const float4*)X)[(size_t)row * (DD / 4) + t];
    float4 b = ((const float4*)W)[(size_t)idx * (DD / 4) + t];
    float dx = a.x - b.x, dy = a.y - b.y, dz = a.z - b.z, dw = a.w - b.w;
    float s = dx * dx + dy * dy + dz * dz + dw * dw;
    #pragma unroll
    for (int o = 16; o; o >>= 1) s += __shfl_down_sync(0xffffffffu, s, o);
    __shared__ float red[4];
    if ((t & 31) == 0) red[t >> 5] = s;
    __syncthreads();
    if (t == 0) {
        float tot = red[0] + red[1] + red[2] + red[3];
        if (mask) {
            atomicAdd(&d_sq, (double)tot);
            atomicAdd(&d_cnt, 1.0);
        }
    }
}

// ---------------- finalize ----------------
__global__ void k_final(float* out) {
    double dl = (d_cnt > 0.0) ? d_sq / (d_cnt * (double)DD) : 0.0;
    out[0] = (float)(d_ot + dl);
}

// ---------------- launch ----------------
extern "C" void kernel_launch(void* const* d_in, const int* in_sizes, int n_in,
                              void* d_out, int out_size) {
    const float* X  = (const float*)d_in[0];
    const float* W  = (const float*)d_in[1];
    const int*   AL = (const int*)d_in[2];
    const float* T  = (const float*)d_in[3];
    float* out = (float*)d_out;

    k_init<<<1, 1024>>>(T, AL);
    k_sqnorm<<<NN, 128>>>(X, 0);
    k_sqnorm<<<MM, 128>>>(W, 1);
    k_scale<<<1, 1024>>>();
    dim3 gg(MM / 128, NN / 128);
    k_gemm<<<gg, 256>>>(X, W);
    k_ginit<<<MM / 256, 256>>>();

    for (int it = 0; it < N_ITERS; it++) {
        k_frow<<<NN / FROWS, 256>>>();
        k_gpart<<<dim3(8, CHUNKS), 256>>>();
        k_gcomb<<<MM / 256, 256>>>();
    }

    k_ot<<<dim3(8, CHUNKS), 256>>>();
    k_dist<<<NN, 128>>>(X, W, AL);
    k_final<<<1, 1>>>(out);
}